// round 14
// baseline (speedup 1.0000x reference)
#include <cuda_runtime.h>
#include <cuda_fp16.h>
#include <math.h>
#include <stdint.h>

#define BB_  2
#define CC   128
#define HH   128
#define WW   128
#define SRR  8
#define MOFF 17
#define IP   289
#define MIDC 144
#define OPC  49
#define HW   (HH*WW)

#define CPAD   320            // 289 padded to 5*64
#define NCHUNK 5
#define NTAP   9

#define CPAD2  192            // 144 padded to 3*64
#define OPAD   56             // 49 padded to 7*8

// ---------------- scratch (static device globals; no runtime allocation) ----------------
__device__ float g_rn [BB_*HW];
__device__ float g_mv [(size_t)BB_*IP*HW];
__device__ float g_att[(size_t)BB_*IP*HW];
__device__ __half g_atth[(size_t)BB_*HW*CPAD];   // NHWC fp16 (conv1 A)
__device__ __half g_midh[(size_t)BB_*HW*CPAD2];  // NHWC fp16 (conv2 A)
__device__ __half g_w1  [NTAP*NCHUNK*MIDC*64];   // [t][c][co][ci] fp16
__device__ __half g_w2  [NTAP*3*OPAD*64];        // [t][c][co][ci] fp16

// ---------------- helpers ----------------
__device__ __forceinline__ uint32_t smem_u32(const void* p) {
    uint32_t a;
    asm("{ .reg .u64 t; cvta.to.shared.u64 t, %1; cvt.u32.u64 %0, t; }" : "=r"(a) : "l"(p));
    return a;
}
#define SWZ(o) ((o) ^ (((o) >> 3) & 0x70))

__device__ __forceinline__ void cpa16(uint32_t saddr, const void* gaddr, uint32_t sz) {
    asm volatile("cp.async.cg.shared.global [%0], [%1], 16, %2;"
                 :: "r"(saddr), "l"(gaddr), "r"(sz));
}
#define CPA_COMMIT() asm volatile("cp.async.commit_group;" ::: "memory")
#define CPA_WAIT0()  asm volatile("cp.async.wait_group 0;" ::: "memory")
#define CPA_WAIT1()  asm volatile("cp.async.wait_group 1;" ::: "memory")

__device__ __forceinline__ void ldsm4(uint32_t addr, uint32_t* r) {
    asm volatile("ldmatrix.sync.aligned.m8n8.x4.shared.b16 {%0,%1,%2,%3}, [%4];"
                 : "=r"(r[0]), "=r"(r[1]), "=r"(r[2]), "=r"(r[3]) : "r"(addr));
}
__device__ __forceinline__ void ldsm2(uint32_t addr, uint32_t* r) {
    asm volatile("ldmatrix.sync.aligned.m8n8.x2.shared.b16 {%0,%1}, [%2];"
                 : "=r"(r[0]), "=r"(r[1]) : "r"(addr));
}
__device__ __forceinline__ void mma16816h(float* d, const uint32_t* a, const uint32_t* b) {
    asm volatile("mma.sync.aligned.m16n8k16.row.col.f32.f16.f16.f32 "
                 "{%0,%1,%2,%3}, {%4,%5,%6,%7}, {%8,%9}, {%0,%1,%2,%3};"
                 : "+f"(d[0]), "+f"(d[1]), "+f"(d[2]), "+f"(d[3])
                 : "r"(a[0]), "r"(a[1]), "r"(a[2]), "r"(a[3]), "r"(b[0]), "r"(b[1]));
}
__device__ __forceinline__ float gelu_exact(float z) {
    return 0.5f * z * (1.f + erff(z * 0.70710678118654752440f));
}
// packed fp32x2 ops (Blackwell)
typedef unsigned long long ull;
__device__ __forceinline__ ull pk2(float a, float b) {
    ull r;
    asm("mov.b64 %0, {%1, %2};" : "=l"(r) : "r"(__float_as_uint(a)), "r"(__float_as_uint(b)));
    return r;
}
__device__ __forceinline__ ull fma2(ull a, ull b, ull c) {
    ull d;
    asm("fma.rn.f32x2 %0, %1, %2, %3;" : "=l"(d) : "l"(a), "l"(b), "l"(c));
    return d;
}
__device__ __forceinline__ void upk2(ull v, float& lo, float& hi) {
    uint32_t l, h;
    asm("mov.b64 {%0, %1}, %2;" : "=r"(l), "=r"(h) : "l"(v));
    lo = __uint_as_float(l); hi = __uint_as_float(h);
}

// ---------------- kernel 1a: per-pixel inverse L2 norm of f1 ----------------
__global__ void k_rnorm(const float* __restrict__ f1) {
    int idx = blockIdx.x * 256 + threadIdx.x;
    if (idx >= BB_*HW) return;
    int b = idx / HW, p = idx % HW;
    const float* base = f1 + (size_t)b*CC*HW + p;
    float s = 0.f;
#pragma unroll 8
    for (int c = 0; c < CC; c++) { float v = base[(size_t)c*HW]; s = fmaf(v, v, s); }
    g_rn[idx] = 1.f / fmaxf(sqrtf(s), 1e-12f);
}

// ---------------- kernel 1b/1c: weight prep (fp16) ----------------
__global__ void k_prepw(const float* __restrict__ w) {
    int i = blockIdx.x * 256 + threadIdx.x;
    if (i >= NTAP*NCHUNK*MIDC*64) return;
    int ci_in = i & 63;
    int co    = (i >> 6) % MIDC;
    int tc    = (i >> 6) / MIDC;
    int c     = tc % NCHUNK;
    int t     = tc / NCHUNK;
    int ci    = c*64 + ci_in;
    float v = (ci < IP) ? w[((size_t)co*IP + ci)*9 + t] : 0.f;
    g_w1[i] = __float2half(v);
}
__global__ void k_prepw2(const float* __restrict__ w) {
    int i = blockIdx.x * 256 + threadIdx.x;
    if (i >= NTAP*3*OPAD*64) return;
    int ci_in = i & 63;
    int co    = (i >> 6) % OPAD;
    int tc    = (i >> 6) / OPAD;
    int c     = tc % 3;
    int t     = tc / 3;
    int ci    = c*64 + ci_in;
    float v = (co < OPC && ci < MIDC) ? w[((size_t)co*MIDC + ci)*9 + t] : 0.f;
    g_w2[i] = __float2half(v);
}

// ---------------- kernel 2: cost volume, QUAD-channel iters, f32x2 FMA ------------------
// 32 iterations, ONE sync each, 3 quad-buffers (dynamic smem: 3*(256+5440) floats).
#define CV_QUAD (4*MOFF*80)      // 5440 floats
#define CV_SMEM ((3*256 + 3*CV_QUAD)*4)
__global__ __launch_bounds__(272, 2) void k_costvol(const float* __restrict__ f1,
                                                    const float* __restrict__ f2) {
    extern __shared__ float dsm[];
    float (*s_x1)[256]     = (float(*)[256])dsm;
    float (*s_f2)[CV_QUAD] = (float(*)[CV_QUAD])(dsm + 3*256);

    const int x0  = blockIdx.x * 64;
    const int h   = blockIdx.y;
    const int b   = blockIdx.z;
    const int tid = threadIdx.x;
    const int g   = tid & 15;
    const int dy  = tid >> 4;

    const float* f1b = f1 + (size_t)b*CC*HW;
    const float* f2b = f2 + (size_t)b*CC*HW;

    // 5 staging slots per thread (4 ch x 340 float4 = 1360 = 5*272 exactly)
    int goff[5]; int chof[5]; uint32_t smoff[5]; uint32_t csz[5];
#pragma unroll
    for (int k = 0; k < 5; k++) {
        int sl = tid + k*272;
        int ch = sl / 340;
        int r4 = sl - ch*340;
        int r = r4 / 20, col4 = (r4 % 20) * 4;
        int gy = h + r - SRR, gx0 = x0 + col4 - SRR;
        bool ok = (gy >= 0 && gy < HH && gx0 >= 0 && gx0 <= WW - 4);
        goff[k]  = ok ? (gy*WW + gx0) : 0;
        chof[k]  = ch;
        csz[k]   = ok ? 16u : 0u;
        smoff[k] = (uint32_t)((ch*(MOFF*80) + r*80 + col4) * 4);
    }
    const uint32_t sb_f2 = smem_u32(&s_f2[0][0]);

    float rnv = 0.f;  const float* x1p = nullptr;
    if (tid < 64) {
        rnv = g_rn[(size_t)b*HW + h*WW + x0 + tid];
        x1p = f1b + h*WW + x0 + tid;
    }

    ull acc2[MOFF][2];
    const ull zz = pk2(0.f, 0.f);
#pragma unroll
    for (int d = 0; d < MOFF; d++) { acc2[d][0] = zz; acc2[d][1] = zz; }

    // prologue: stage quad 0 into buffer 0
    {
#pragma unroll
        for (int k = 0; k < 5; k++)
            cpa16(sb_f2 + smoff[k], f2b + (size_t)chof[k]*HW + goff[k], csz[k]);
        CPA_COMMIT();
    }
    float x1c[4] = {0.f,0.f,0.f,0.f}, x1n[4] = {0.f,0.f,0.f,0.f};
    if (tid < 64) {
#pragma unroll
        for (int k = 0; k < 4; k++) x1c[k] = x1p[(size_t)k*HW];
    }

    for (int cp = 0; cp < CC/4; cp++) {
        const int buf = cp - (cp/3)*3;
        if (cp + 1 < CC/4) {
            if (tid < 64) {
#pragma unroll
                for (int k = 0; k < 4; k++) x1n[k] = x1p[(size_t)(4*cp+4+k)*HW];
            }
            const int nbuf = (cp+1) - ((cp+1)/3)*3;
            const float* src = f2b + (size_t)(4*cp+4)*HW;
            uint32_t base = sb_f2 + (uint32_t)nbuf * (CV_QUAD*4);
#pragma unroll
            for (int k = 0; k < 5; k++)
                cpa16(base + smoff[k], src + (size_t)chof[k]*HW + goff[k], csz[k]);
            CPA_COMMIT();
            CPA_WAIT1();
        } else {
            CPA_WAIT0();
        }
        if (tid < 64) {
#pragma unroll
            for (int k = 0; k < 4; k++) s_x1[buf][k*64 + tid] = x1c[k] * rnv;
        }
        __syncthreads();

#pragma unroll
        for (int ch2 = 0; ch2 < 4; ch2++) {
            float4 x1v = *(const float4*)&s_x1[buf][ch2*64 + g*4];
            ull x1a = pk2(x1v.x, x1v.y);
            ull x1b = pk2(x1v.z, x1v.w);
            float f2v[20];
            const float* row = &s_f2[buf][ch2*(MOFF*80) + dy*80 + g*4];
#pragma unroll
            for (int q = 0; q < 5; q++) {
                float4 t = *(const float4*)&row[q*4];
                f2v[q*4+0] = t.x; f2v[q*4+1] = t.y; f2v[q*4+2] = t.z; f2v[q*4+3] = t.w;
            }
            ull e[10], o[9];
#pragma unroll
            for (int k = 0; k < 10; k++) e[k] = pk2(f2v[2*k], f2v[2*k+1]);
#pragma unroll
            for (int k = 0; k < 9; k++)  o[k] = pk2(f2v[2*k+1], f2v[2*k+2]);
#pragma unroll
            for (int dx = 0; dx < MOFF; dx++) {
                ull p0 = (dx & 1) ? o[(dx-1)>>1] : e[dx>>1];
                ull p1 = (dx & 1) ? o[(dx+1)>>1] : e[(dx>>1)+1];
                acc2[dx][0] = fma2(x1a, p0, acc2[dx][0]);
                acc2[dx][1] = fma2(x1b, p1, acc2[dx][1]);
            }
        }
#pragma unroll
        for (int k = 0; k < 4; k++) x1c[k] = x1n[k];
    }

#pragma unroll
    for (int dx = 0; dx < MOFF; dx++) {
        float4 oV;
        float* op = (float*)&oV;
        upk2(acc2[dx][0], op[0], op[1]);
        upk2(acc2[dx][1], op[2], op[3]);
#pragma unroll
        for (int j = 0; j < 4; j++) {
            float v = op[j] * 0.0078125f;
            op[j] = v > 0.f ? v : 0.1f * v;
        }
        int ch = dy*MOFF + dx;
        *(float4*)&g_mv[(((size_t)b*IP + ch)*HH + h)*WW + x0 + g*4] = oV;
    }
}

// ---------------- kernel 3: depthwise 7x7 att + bias, 32x16 tile (2 rows/thread) --------
__global__ void k_att(const float* __restrict__ att_w, const float* __restrict__ att_b) {
    __shared__ float s_in[22*40];
    __shared__ float s_w[49];

    const int bz = blockIdx.z;
    const int b  = bz / IP;
    const int ch = bz % IP;
    const int x0 = blockIdx.x * 32;
    const int y0 = blockIdx.y * 16;
    const int tid = threadIdx.x;

    const float* mvp = g_mv + ((size_t)b*IP + ch)*HW;
    for (int i = tid; i < 22*38; i += 256) {
        int r = i / 38, cl = i - r*38;
        int gy = y0 + r - 3, gx = x0 + cl - 3;
        s_in[r*40 + cl] = (gy >= 0 && gy < HH && gx >= 0 && gx < WW) ? mvp[gy*WW + gx] : 0.f;
    }
    if (tid < 49) s_w[tid] = att_w[ch*49 + tid];
    __syncthreads();

    const int tx = tid & 31, ty = tid >> 5;
    const float bias = att_b[ch];
    float* outp = g_att + ((size_t)b*IP + ch)*HW;
#pragma unroll
    for (int half = 0; half < 2; half++) {
        int yy = ty + half*8;
        float s = bias;
#pragma unroll
        for (int ky = 0; ky < 7; ky++)
#pragma unroll
            for (int kx = 0; kx < 7; kx++)
                s = fmaf(s_w[ky*7+kx], s_in[(yy+ky)*40 + tx + kx], s);
        float center = s_in[(yy+3)*40 + tx + 3];
        outp[(size_t)(y0+yy)*WW + x0 + tx] = center * s;
    }
}

// ---------------- kernel 4: transpose NCHW fp32 -> NHWC fp16 (C padded 320) ----
__global__ __launch_bounds__(256) void k_nhwc() {
    __shared__ float s[32][33];
    const int tid = threadIdx.x;
    const int tx = tid & 31, ty = tid >> 5;
    const int px0 = blockIdx.x * 32;
    const int ch0 = blockIdx.y * 32;
    const int b   = blockIdx.z;

#pragma unroll
    for (int j = 0; j < 4; j++) {
        int ch = ch0 + j*8 + ty;
        s[j*8 + ty][tx] = (ch < IP) ? g_att[((size_t)b*IP + ch)*HW + px0 + tx] : 0.f;
    }
    __syncthreads();
#pragma unroll
    for (int j = 0; j < 4; j++) {
        int px = px0 + j*8 + ty;
        float v = s[tx][j*8 + ty];
        g_atth[(size_t)(b*HW + px)*CPAD + ch0 + tx] = __float2half(v);
    }
}

// ================= kernel 5: conv1 implicit GEMM pure fp16, 512 threads, M=256 =========
#define G1_ASPL 67584                 // 528 rows * 128B (single A)
#define G1_BOFF G1_ASPL               // 67584
#define G1_BSTG 18432                 // 144 rows * 128B
#define G1_BN   (G1_BOFF + 2*G1_BSTG) // 104448
#define G1_SMEM (G1_BN + 3*MIDC*4 + 64)
#define G1_THREADS 512

__device__ __forceinline__ void g1_stageA(uint32_t sbA, int tid, int c, int b, int y0) {
#pragma unroll
    for (int j = 0; j < 9; j++) {
        int i = tid + j*G1_THREADS;
        if (i < 4224) {
            int row = i >> 3, q = i & 7;
            int yrel = row / 132;
            int pxh  = row - yrel*132;
            int ysrc = y0 - 1 + yrel, xsrc = pxh - 1;
            bool ok = ((unsigned)ysrc < (unsigned)HH) && ((unsigned)xsrc < (unsigned)WW);
            const void* gp = g_atth + ((size_t)((b*HH + (ok?ysrc:0))*WW + (ok?xsrc:0)))*CPAD + c*64 + q*8;
            cpa16(sbA + SWZ((uint32_t)(row*128 + q*16)), gp, ok ? 16u : 0u);
        }
    }
}
__device__ __forceinline__ void g1_stageB(uint32_t sbB, int tid, int t, int c) {
    const __half* w = g_w1 + (size_t)(t*NCHUNK + c)*MIDC*64;
#pragma unroll
    for (int j = 0; j < 3; j++) {
        int i = tid + j*G1_THREADS;
        if (i < 1152) {
            int row = i >> 3, q = i & 7;
            cpa16(sbB + SWZ((uint32_t)(row*128 + q*16)), w + row*64 + q*8, 16u);
        }
    }
}

__global__ __launch_bounds__(G1_THREADS, 1) void k_gemm1(const float* __restrict__ bg,
                                                         const float* __restrict__ bb,
                                                         const float* __restrict__ bm,
                                                         const float* __restrict__ bv) {
    extern __shared__ char smem[];
    const int tid  = threadIdx.x;
    const int wid  = tid >> 5, lane = tid & 31;
    const int y0   = (blockIdx.x & 63) * 2;
    const int b    = blockIdx.x >> 6;
    const uint32_t sb = smem_u32(smem);

    float* sScale = (float*)(smem + G1_BN);
    float* sMean  = sScale + MIDC;
    float* sBeta  = sMean + MIDC;
    if (tid < MIDC) {
        sScale[tid] = bg[tid] * rsqrtf(bv[tid] + 1e-5f);
        sMean[tid]  = bm[tid];
        sBeta[tid]  = bb[tid];
    }

    const int wm = wid >> 1, wn = wid & 1;
    const int ywarp = wm >> 2;
    const int pxb   = (wm & 3) * 32;

    const int gA = lane >> 3;
    const int arow_off = (lane & 7) + ((gA & 1) << 3);
    const uint32_t acol_g = (uint32_t)((gA >> 1) << 4);
    const uint32_t swzx   = (uint32_t)((lane & 7) << 4);
    const int brow_off = ((gA >> 1) << 3) + (lane & 7);
    const uint32_t bcol_g = (uint32_t)((gA & 1) << 4);
    const int l2 = lane & 15;
    const int b2row_off = 64 + (l2 & 7);
    const uint32_t b2col_g = (uint32_t)((l2 >> 3) << 4);
    const uint32_t swz2   = (uint32_t)((l2 & 7) << 4);

    float acc[2][9][4];
#pragma unroll
    for (int mf = 0; mf < 2; mf++)
#pragma unroll
        for (int nf = 0; nf < 9; nf++)
#pragma unroll
            for (int k = 0; k < 4; k++) acc[mf][nf][k] = 0.f;

    g1_stageA(sb, tid, 0, b, y0);
    g1_stageB(sb + G1_BOFF, tid, 0, 0);
    CPA_COMMIT();

    int s = 0;
    for (int c = 0; c < NCHUNK; c++) {
        if (c > 0) { g1_stageA(sb, tid, c, b, y0); CPA_COMMIT(); }
        for (int t = 0; t < NTAP; t++, s++) {
            if (s + 1 < NTAP*NCHUNK) {
                int t1 = (t + 1 < NTAP) ? t + 1 : 0;
                int c1 = (t + 1 < NTAP) ? c : c + 1;
                g1_stageB(sb + G1_BOFF + (uint32_t)((s + 1) & 1)*G1_BSTG, tid, t1, c1);
                CPA_COMMIT();
                CPA_WAIT1();
            } else {
                CPA_WAIT0();
            }
            __syncthreads();

            const int ky = t / 3, kx = t - ky*3;
            const uint32_t bBase = sb + G1_BOFF + (uint32_t)(s & 1)*G1_BSTG + (uint32_t)(wn*72)*128;
            const int arbase = (ky + ywarp)*132 + pxb + kx;

#pragma unroll
            for (int ks = 0; ks < 4; ks++) {
                uint32_t bh[9][2];
                const uint32_t colB = ((uint32_t)(ks * 32) + bcol_g) ^ swzx;
#pragma unroll
                for (int nf = 0; nf < 8; nf += 2) {
                    uint32_t rb = (uint32_t)(nf * 8 + brow_off) * 128;
                    uint32_t tmp[4];
                    ldsm4(bBase + rb + colB, tmp);
                    bh[nf][0] = tmp[0]; bh[nf][1] = tmp[1];
                    bh[nf+1][0] = tmp[2]; bh[nf+1][1] = tmp[3];
                }
                {
                    const uint32_t colB2 = ((uint32_t)(ks * 32) + b2col_g) ^ swz2;
                    uint32_t rb2 = (uint32_t)b2row_off * 128;
                    ldsm2(bBase + rb2 + colB2, bh[8]);
                }
                const uint32_t colA_base = (uint32_t)(ks * 32) + acol_g;
#pragma unroll
                for (int mf = 0; mf < 2; mf++) {
                    int arow = arbase + mf*16 + arow_off;
                    uint32_t aaddr = sb + (uint32_t)arow*128
                                   + (colA_base ^ (((uint32_t)arow & 7) << 4));
                    uint32_t ah[4];
                    ldsm4(aaddr, ah);
#pragma unroll
                    for (int nf = 0; nf < 9; nf++)
                        mma16816h(acc[mf][nf], ah, bh[nf]);
                }
            }
            __syncthreads();
        }
    }

    // epilogue: BN + GELU -> fp16 NHWC (CPAD2) for gemm2
    const int yout = y0 + ywarp;
#pragma unroll
    for (int mf = 0; mf < 2; mf++)
#pragma unroll
        for (int nf = 0; nf < 9; nf++) {
            int co0 = wn * 72 + nf * 8 + (lane & 3) * 2;
            int x0  = pxb + mf * 16 + (lane >> 2);
#pragma unroll
            for (int hr = 0; hr < 2; hr++) {
                int x = x0 + hr * 8;
                float v0 = acc[mf][nf][hr * 2 + 0];
                float v1 = acc[mf][nf][hr * 2 + 1];
                float g0 = gelu_exact((v0 - sMean[co0]) * sScale[co0] + sBeta[co0]);
                float g1 = gelu_exact((v1 - sMean[co0+1]) * sScale[co0+1] + sBeta[co0+1]);
                __half2 ph; ph.x = __float2half(g0); ph.y = __float2half(g1);
                *(__half2*)&g_midh[((size_t)b*HW + yout*WW + x) * CPAD2 + co0] = ph;
            }
        }
}

// ================= kernel 6: conv2 implicit GEMM pure fp16, 512 threads, M=256 =========
#define G2_ASPL 67584
#define G2_BOFF G2_ASPL
#define G2_BSTG 7168
#define G2_BN   (G2_BOFF + 2*G2_BSTG)   // 81920
#define G2_SMEM (G2_BN + 3*OPC*4 + 64)
#define G2_THREADS 512

__device__ __forceinline__ void g2_stageA(uint32_t sbA, int tid, int c, int b, int y0) {
#pragma unroll
    for (int j = 0; j < 9; j++) {
        int i = tid + j*G2_THREADS;
        if (i < 4224) {
            int row = i >> 3, q = i & 7;
            int yrel = row / 132;
            int pxh  = row - yrel*132;
            int ysrc = y0 - 1 + yrel, xsrc = pxh - 1;
            bool ok = ((unsigned)ysrc < (unsigned)HH) && ((unsigned)xsrc < (unsigned)WW);
            const void* gp = g_midh + ((size_t)((b*HH + (ok?ysrc:0))*WW + (ok?xsrc:0)))*CPAD2 + c*64 + q*8;
            cpa16(sbA + SWZ((uint32_t)(row*128 + q*16)), gp, ok ? 16u : 0u);
        }
    }
}
__device__ __forceinline__ void g2_stageB(uint32_t sbB, int tid, int t, int c) {
    const __half* w = g_w2 + (size_t)(t*3 + c)*OPAD*64;
    if (tid < OPAD*8) {
        int row = tid >> 3, q = tid & 7;
        cpa16(sbB + SWZ((uint32_t)(row*128 + q*16)), w + row*64 + q*8, 16u);
    }
}

__global__ __launch_bounds__(G2_THREADS, 1) void k_gemm2(const float* __restrict__ bg,
                                                         const float* __restrict__ bb,
                                                         const float* __restrict__ bm,
                                                         const float* __restrict__ bv,
                                                         float* __restrict__ dout) {
    extern __shared__ char smem[];
    const int tid  = threadIdx.x;
    const int wid  = tid >> 5, lane = tid & 31;
    const int y0   = (blockIdx.x & 63) * 2;
    const int b    = blockIdx.x >> 6;
    const uint32_t sb = smem_u32(smem);

    float* sScale = (float*)(smem + G2_BN);
    float* sMean  = sScale + OPC;
    float* sBeta  = sMean + OPC;
    if (tid < OPC) {
        sScale[tid] = bg[tid] * rsqrtf(bv[tid] + 1e-5f);
        sMean[tid]  = bm[tid];
        sBeta[tid]  = bb[tid];
    }

    const int ywarp = wid >> 3;          // 0/1
    const int pxb   = (wid & 7) * 16;    // 16 px per warp

    const int gA = lane >> 3;
    const int arow_off = (lane & 7) + ((gA & 1) << 3);
    const uint32_t acol_g = (uint32_t)((gA >> 1) << 4);
    const uint32_t swzx   = (uint32_t)((lane & 7) << 4);
    const int brow_off = ((gA >> 1) << 3) + (lane & 7);
    const uint32_t bcol_g = (uint32_t)((gA & 1) << 4);
    const int l2 = lane & 15;
    const int b2row_off = 48 + (l2 & 7);
    const uint32_t b2col_g = (uint32_t)((l2 >> 3) << 4);
    const uint32_t swz2   = (uint32_t)((l2 & 7) << 4);

    float acc[7][4];
#pragma unroll
    for (int nf = 0; nf < 7; nf++)
#pragma unroll
        for (int k = 0; k < 4; k++) acc[nf][k] = 0.f;

    g2_stageA(sb, tid, 0, b, y0);
    g2_stageB(sb + G2_BOFF, tid, 0, 0);
    CPA_COMMIT();

    int s = 0;
    for (int c = 0; c < 3; c++) {
        if (c > 0) { g2_stageA(sb, tid, c, b, y0); CPA_COMMIT(); }
        for (int t = 0; t < NTAP; t++, s++) {
            if (s + 1 < NTAP*3) {
                int t1 = (t + 1 < NTAP) ? t + 1 : 0;
                int c1 = (t + 1 < NTAP) ? c : c + 1;
                g2_stageB(sb + G2_BOFF + (uint32_t)((s + 1) & 1)*G2_BSTG, tid, t1, c1);
                CPA_COMMIT();
                CPA_WAIT1();
            } else {
                CPA_WAIT0();
            }
            __syncthreads();

            const int ky = t / 3, kx = t - ky*3;
            const uint32_t bBase = sb + G2_BOFF + (uint32_t)(s & 1)*G2_BSTG;
            const int arbase = (ky + ywarp)*132 + pxb + kx;

#pragma unroll
            for (int ks = 0; ks < 4; ks++) {
                uint32_t bh[7][2];
                const uint32_t colB = ((uint32_t)(ks * 32) + bcol_g) ^ swzx;
#pragma unroll
                for (int nf = 0; nf < 6; nf += 2) {
                    uint32_t rb = (uint32_t)(nf * 8 + brow_off) * 128;
                    uint32_t tmp[4];
                    ldsm4(bBase + rb + colB, tmp);
                    bh[nf][0] = tmp[0]; bh[nf][1] = tmp[1];
                    bh[nf+1][0] = tmp[2]; bh[nf+1][1] = tmp[3];
                }
                {
                    const uint32_t colB2 = ((uint32_t)(ks * 32) + b2col_g) ^ swz2;
                    uint32_t rb2 = (uint32_t)b2row_off * 128;
                    ldsm2(bBase + rb2 + colB2, bh[6]);
                }
                const uint32_t colA_base = (uint32_t)(ks * 32) + acol_g;
                {
                    int arow = arbase + arow_off;
                    uint32_t aaddr = sb + (uint32_t)arow*128
                                   + (colA_base ^ (((uint32_t)arow & 7) << 4));
                    uint32_t ah[4];
                    ldsm4(aaddr, ah);
#pragma unroll
                    for (int nf = 0; nf < 7; nf++)
                        mma16816h(acc[nf], ah, bh[nf]);
                }
            }
            __syncthreads();
        }
    }

    const int yout = y0 + ywarp;
#pragma unroll
    for (int nf = 0; nf < 7; nf++) {
        int co0 = nf * 8 + (lane & 3) * 2;
        int x0  = pxb + (lane >> 2);
#pragma unroll
        for (int hr = 0; hr < 2; hr++) {
            int x = x0 + hr * 8;
#pragma unroll
            for (int dc = 0; dc < 2; dc++) {
                int co = co0 + dc;
                if (co < OPC) {
                    float v = acc[nf][hr * 2 + dc];
                    float gel = gelu_exact((v - sMean[co]) * sScale[co] + sBeta[co]);
                    dout[(((size_t)b*OPC + co)*HH + yout)*WW + x] = gel;
                }
            }
        }
    }
}

// ---------------- launch ----------------
extern "C" void kernel_launch(void* const* d_in, const int* in_sizes, int n_in,
                              void* d_out, int out_size) {
    const float* f1    = (const float*)d_in[0];
    const float* f2    = (const float*)d_in[1];
    const float* att_w = (const float*)d_in[2];
    const float* att_b = (const float*)d_in[3];
    const float* c1_w  = (const float*)d_in[4];
    const float* bn1_g = (const float*)d_in[5];
    const float* bn1_b = (const float*)d_in[6];
    const float* bn1_m = (const float*)d_in[7];
    const float* bn1_v = (const float*)d_in[8];
    const float* c2_w  = (const float*)d_in[9];
    const float* bn2_g = (const float*)d_in[10];
    const float* bn2_b = (const float*)d_in[11];
    const float* bn2_m = (const float*)d_in[12];
    const float* bn2_v = (const float*)d_in[13];

    cudaFuncSetAttribute(k_costvol, cudaFuncAttributeMaxDynamicSharedMemorySize, CV_SMEM);
    cudaFuncSetAttribute(k_gemm1, cudaFuncAttributeMaxDynamicSharedMemorySize, G1_SMEM);
    cudaFuncSetAttribute(k_gemm2, cudaFuncAttributeMaxDynamicSharedMemorySize, G2_SMEM);

    k_rnorm<<<(BB_*HW + 255)/256, 256>>>(f1);
    k_prepw<<<(NTAP*NCHUNK*MIDC*64 + 255)/256, 256>>>(c1_w);
    k_prepw2<<<(NTAP*3*OPAD*64 + 255)/256, 256>>>(c2_w);
    k_costvol<<<dim3(WW/64, HH, BB_), 272, CV_SMEM>>>(f1, f2);   // 4th launch -> profiled
    k_att<<<dim3(WW/32, HH/16, BB_*IP), 256>>>(att_w, att_b);
    k_nhwc<<<dim3(HW/32, (IP+31)/32, BB_), 256>>>();
    k_gemm1<<<BB_*64, G1_THREADS, G1_SMEM>>>(bn1_g, bn1_b, bn1_m, bn1_v);
    k_gemm2<<<BB_*64, G2_THREADS, G2_SMEM>>>(bn2_g, bn2_b, bn2_m, bn2_v, (float*)d_out);
}

// round 15
// speedup vs baseline: 1.0620x; 1.0620x over previous
#include <cuda_runtime.h>
#include <cuda_fp16.h>
#include <math.h>
#include <stdint.h>

#define BB_  2
#define CC   128
#define HH   128
#define WW   128
#define SRR  8
#define MOFF 17
#define IP   289
#define MIDC 144
#define OPC  49
#define HW   (HH*WW)

#define CPAD   320            // 289 padded to 5*64
#define NCHUNK 5
#define NTAP   9

#define CPAD2  192            // 144 padded to 3*64
#define OPAD   56             // 49 padded to 7*8

// ---------------- scratch (static device globals; no runtime allocation) ----------------
__device__ float g_rn [BB_*HW];
__device__ float g_mv [(size_t)BB_*IP*HW];
__device__ float g_att[(size_t)BB_*IP*HW];
__device__ __half g_atth[(size_t)BB_*HW*CPAD];   // NHWC fp16 (conv1 A)
__device__ __half g_midh[(size_t)BB_*HW*CPAD2];  // NHWC fp16 (conv2 A)
__device__ __half g_w1  [NTAP*NCHUNK*MIDC*64];   // [t][c][co][ci] fp16
__device__ __half g_w2  [NTAP*3*OPAD*64];        // [t][c][co][ci] fp16

// ---------------- helpers ----------------
__device__ __forceinline__ uint32_t smem_u32(const void* p) {
    uint32_t a;
    asm("{ .reg .u64 t; cvta.to.shared.u64 t, %1; cvt.u32.u64 %0, t; }" : "=r"(a) : "l"(p));
    return a;
}
#define SWZ(o) ((o) ^ (((o) >> 3) & 0x70))

__device__ __forceinline__ void cpa16(uint32_t saddr, const void* gaddr, uint32_t sz) {
    asm volatile("cp.async.cg.shared.global [%0], [%1], 16, %2;"
                 :: "r"(saddr), "l"(gaddr), "r"(sz));
}
#define CPA_COMMIT() asm volatile("cp.async.commit_group;" ::: "memory")
#define CPA_WAIT0()  asm volatile("cp.async.wait_group 0;" ::: "memory")
#define CPA_WAIT1()  asm volatile("cp.async.wait_group 1;" ::: "memory")

__device__ __forceinline__ void ldsm4(uint32_t addr, uint32_t* r) {
    asm volatile("ldmatrix.sync.aligned.m8n8.x4.shared.b16 {%0,%1,%2,%3}, [%4];"
                 : "=r"(r[0]), "=r"(r[1]), "=r"(r[2]), "=r"(r[3]) : "r"(addr));
}
__device__ __forceinline__ void ldsm2(uint32_t addr, uint32_t* r) {
    asm volatile("ldmatrix.sync.aligned.m8n8.x2.shared.b16 {%0,%1}, [%2];"
                 : "=r"(r[0]), "=r"(r[1]) : "r"(addr));
}
__device__ __forceinline__ void mma16816h(float* d, const uint32_t* a, const uint32_t* b) {
    asm volatile("mma.sync.aligned.m16n8k16.row.col.f32.f16.f16.f32 "
                 "{%0,%1,%2,%3}, {%4,%5,%6,%7}, {%8,%9}, {%0,%1,%2,%3};"
                 : "+f"(d[0]), "+f"(d[1]), "+f"(d[2]), "+f"(d[3])
                 : "r"(a[0]), "r"(a[1]), "r"(a[2]), "r"(a[3]), "r"(b[0]), "r"(b[1]));
}
__device__ __forceinline__ float gelu_exact(float z) {
    return 0.5f * z * (1.f + erff(z * 0.70710678118654752440f));
}

// ---------------- kernel 1: fused prep (rnorm | conv1 wprep | conv2 wprep) ----------------
#define PREP_RN_BLKS  128                       // BB_*HW/256
#define PREP_W1_BLKS  1620                      // 9*5*144*64/256
#define PREP_W2_BLKS  378                       // 9*3*56*64/256
__global__ void k_prep(const float* __restrict__ f1,
                       const float* __restrict__ c1w,
                       const float* __restrict__ c2w) {
    const int bx = blockIdx.x;
    const int tid = threadIdx.x;
    if (bx < PREP_RN_BLKS) {
        int idx = bx * 256 + tid;
        int b = idx / HW, p = idx % HW;
        const float* base = f1 + (size_t)b*CC*HW + p;
        float s = 0.f;
#pragma unroll 8
        for (int c = 0; c < CC; c++) { float v = base[(size_t)c*HW]; s = fmaf(v, v, s); }
        g_rn[idx] = 1.f / fmaxf(sqrtf(s), 1e-12f);
    } else if (bx < PREP_RN_BLKS + PREP_W1_BLKS) {
        int i = (bx - PREP_RN_BLKS) * 256 + tid;
        int ci_in = i & 63;
        int co    = (i >> 6) % MIDC;
        int tc    = (i >> 6) / MIDC;
        int c     = tc % NCHUNK;
        int t     = tc / NCHUNK;
        int ci    = c*64 + ci_in;
        float v = (ci < IP) ? c1w[((size_t)co*IP + ci)*9 + t] : 0.f;
        g_w1[i] = __float2half(v);
    } else {
        int i = (bx - PREP_RN_BLKS - PREP_W1_BLKS) * 256 + tid;
        int ci_in = i & 63;
        int co    = (i >> 6) % OPAD;
        int tc    = (i >> 6) / OPAD;
        int c     = tc % 3;
        int t     = tc / 3;
        int ci    = c*64 + ci_in;
        float v = (co < OPC && ci < MIDC) ? c2w[((size_t)co*MIDC + ci)*9 + t] : 0.f;
        g_w2[i] = __float2half(v);
    }
}

// ---------------- kernel 2: cost volume, channel-PAIR per iteration, 3 pair-buffers ------
#define CV_PAIR (2*MOFF*80)      // 2720 floats
__global__ __launch_bounds__(272, 2) void k_costvol(const float* __restrict__ f1,
                                                    const float* __restrict__ f2) {
    __shared__ float s_x1[3][128];
    __shared__ float s_f2[3][CV_PAIR];

    const int x0  = blockIdx.x * 64;
    const int h   = blockIdx.y;
    const int b   = blockIdx.z;
    const int tid = threadIdx.x;
    const int g   = tid & 15;
    const int dy  = tid >> 4;

    const float* f1b = f1 + (size_t)b*CC*HW;
    const float* f2b = f2 + (size_t)b*CC*HW;

    int goff[3]; int chof[3]; uint32_t smoff[3]; uint32_t csz[3]; int nslot = 2;
    {
        int slots[3] = { tid, tid + 272, tid + 544 };
        if (slots[2] < 680) nslot = 3;
#pragma unroll
        for (int k = 0; k < 3; k++) {
            int sl = slots[k] < 680 ? slots[k] : 0;
            int ch = sl >= 340;
            int r4 = sl - ch*340;
            int r = r4 / 20, col4 = (r4 % 20) * 4;
            int gy = h + r - SRR, gx0 = x0 + col4 - SRR;
            bool ok = (gy >= 0 && gy < HH && gx0 >= 0 && gx0 <= WW - 4);
            goff[k]  = ok ? (gy*WW + gx0) : 0;
            chof[k]  = ch;
            csz[k]   = ok ? 16u : 0u;
            smoff[k] = (uint32_t)((ch*(MOFF*80) + r*80 + col4) * 4);
        }
    }
    const uint32_t sb_f2 = smem_u32(&s_f2[0][0]);

    float rnv = 0.f;  const float* x1p = nullptr;
    if (tid < 64) {
        rnv = g_rn[(size_t)b*HW + h*WW + x0 + tid];
        x1p = f1b + h*WW + x0 + tid;
    }

    float acc[MOFF][4];
#pragma unroll
    for (int d = 0; d < MOFF; d++)
#pragma unroll
        for (int j = 0; j < 4; j++) acc[d][j] = 0.f;

    {
#pragma unroll
        for (int k = 0; k < 3; k++) {
            if (k < nslot)
                cpa16(sb_f2 + smoff[k], f2b + (size_t)chof[k]*HW + goff[k], csz[k]);
        }
        CPA_COMMIT();
    }
    float x1c0 = 0.f, x1c1 = 0.f, x1n0 = 0.f, x1n1 = 0.f;
    if (tid < 64) { x1c0 = x1p[0]; x1c1 = x1p[HW]; }

    for (int cp = 0; cp < CC/2; cp++) {
        const int buf = cp - (cp/3)*3;
        if (cp + 1 < CC/2) {
            if (tid < 64) {
                x1n0 = x1p[(size_t)(2*cp+2)*HW];
                x1n1 = x1p[(size_t)(2*cp+3)*HW];
            }
            const int nbuf = (cp+1) - ((cp+1)/3)*3;
            const float* src = f2b + (size_t)(2*cp+2)*HW;
            uint32_t base = sb_f2 + (uint32_t)nbuf * (CV_PAIR*4);
#pragma unroll
            for (int k = 0; k < 3; k++) {
                if (k < nslot)
                    cpa16(base + smoff[k], src + (size_t)chof[k]*HW + goff[k], csz[k]);
            }
            CPA_COMMIT();
            CPA_WAIT1();
        } else {
            CPA_WAIT0();
        }
        if (tid < 64) {
            s_x1[buf][tid]      = x1c0 * rnv;
            s_x1[buf][64 + tid] = x1c1 * rnv;
        }
        __syncthreads();

#pragma unroll
        for (int ch2 = 0; ch2 < 2; ch2++) {
            float4 x1v = *(const float4*)&s_x1[buf][ch2*64 + g*4];
            float f2v[20];
            const float* row = &s_f2[buf][ch2*(MOFF*80) + dy*80 + g*4];
#pragma unroll
            for (int q = 0; q < 5; q++) {
                float4 t = *(const float4*)&row[q*4];
                f2v[q*4+0] = t.x; f2v[q*4+1] = t.y; f2v[q*4+2] = t.z; f2v[q*4+3] = t.w;
            }
#pragma unroll
            for (int dx = 0; dx < MOFF; dx++) {
                acc[dx][0] = fmaf(x1v.x, f2v[dx+0], acc[dx][0]);
                acc[dx][1] = fmaf(x1v.y, f2v[dx+1], acc[dx][1]);
                acc[dx][2] = fmaf(x1v.z, f2v[dx+2], acc[dx][2]);
                acc[dx][3] = fmaf(x1v.w, f2v[dx+3], acc[dx][3]);
            }
        }
        x1c0 = x1n0;
        x1c1 = x1n1;
    }

#pragma unroll
    for (int dx = 0; dx < MOFF; dx++) {
        float4 o;
        float* op = (float*)&o;
#pragma unroll
        for (int j = 0; j < 4; j++) {
            float v = acc[dx][j] * 0.0078125f;
            op[j] = v > 0.f ? v : 0.1f * v;
        }
        int ch = dy*MOFF + dx;
        *(float4*)&g_mv[(((size_t)b*IP + ch)*HH + h)*WW + x0 + g*4] = o;
    }
}

// ---------------- kernel 3: depthwise 7x7 att + bias, 32x16 tile (2 rows/thread) --------
__global__ void k_att(const float* __restrict__ att_w, const float* __restrict__ att_b) {
    __shared__ float s_in[22*40];
    __shared__ float s_w[49];

    const int bz = blockIdx.z;
    const int b  = bz / IP;
    const int ch = bz % IP;
    const int x0 = blockIdx.x * 32;
    const int y0 = blockIdx.y * 16;
    const int tid = threadIdx.x;

    const float* mvp = g_mv + ((size_t)b*IP + ch)*HW;
    for (int i = tid; i < 22*38; i += 256) {
        int r = i / 38, cl = i - r*38;
        int gy = y0 + r - 3, gx = x0 + cl - 3;
        s_in[r*40 + cl] = (gy >= 0 && gy < HH && gx >= 0 && gx < WW) ? mvp[gy*WW + gx] : 0.f;
    }
    if (tid < 49) s_w[tid] = att_w[ch*49 + tid];
    __syncthreads();

    const int tx = tid & 31, ty = tid >> 5;
    const float bias = att_b[ch];
    float* outp = g_att + ((size_t)b*IP + ch)*HW;
#pragma unroll
    for (int half = 0; half < 2; half++) {
        int yy = ty + half*8;
        float s = bias;
#pragma unroll
        for (int ky = 0; ky < 7; ky++)
#pragma unroll
            for (int kx = 0; kx < 7; kx++)
                s = fmaf(s_w[ky*7+kx], s_in[(yy+ky)*40 + tx + kx], s);
        float center = s_in[(yy+3)*40 + tx + 3];
        outp[(size_t)(y0+yy)*WW + x0 + tx] = center * s;
    }
}

// ---------------- kernel 4: transpose NCHW fp32 -> NHWC fp16 (C padded 320) ----
__global__ __launch_bounds__(256) void k_nhwc() {
    __shared__ float s[32][33];
    const int tid = threadIdx.x;
    const int tx = tid & 31, ty = tid >> 5;
    const int px0 = blockIdx.x * 32;
    const int ch0 = blockIdx.y * 32;
    const int b   = blockIdx.z;

#pragma unroll
    for (int j = 0; j < 4; j++) {
        int ch = ch0 + j*8 + ty;
        s[j*8 + ty][tx] = (ch < IP) ? g_att[((size_t)b*IP + ch)*HW + px0 + tx] : 0.f;
    }
    __syncthreads();
#pragma unroll
    for (int j = 0; j < 4; j++) {
        int px = px0 + j*8 + ty;
        float v = s[tx][j*8 + ty];
        g_atth[(size_t)(b*HW + px)*CPAD + ch0 + tx] = __float2half(v);
    }
}

// ================= kernel 5: conv1 implicit GEMM pure fp16, 512 threads, M=256 =========
#define G1_ASPL 67584                 // 528 rows * 128B (single A)
#define G1_BOFF G1_ASPL               // 67584
#define G1_BSTG 18432                 // 144 rows * 128B
#define G1_BN   (G1_BOFF + 2*G1_BSTG) // 104448
#define G1_SMEM (G1_BN + 3*MIDC*4 + 64)
#define G1_THREADS 512

__device__ __forceinline__ void g1_stageA(uint32_t sbA, int tid, int c, int b, int y0) {
#pragma unroll
    for (int j = 0; j < 9; j++) {
        int i = tid + j*G1_THREADS;
        if (i < 4224) {
            int row = i >> 3, q = i & 7;
            int yrel = row / 132;
            int pxh  = row - yrel*132;
            int ysrc = y0 - 1 + yrel, xsrc = pxh - 1;
            bool ok = ((unsigned)ysrc < (unsigned)HH) && ((unsigned)xsrc < (unsigned)WW);
            const void* gp = g_atth + ((size_t)((b*HH + (ok?ysrc:0))*WW + (ok?xsrc:0)))*CPAD + c*64 + q*8;
            cpa16(sbA + SWZ((uint32_t)(row*128 + q*16)), gp, ok ? 16u : 0u);
        }
    }
}
__device__ __forceinline__ void g1_stageB(uint32_t sbB, int tid, int t, int c) {
    const __half* w = g_w1 + (size_t)(t*NCHUNK + c)*MIDC*64;
#pragma unroll
    for (int j = 0; j < 3; j++) {
        int i = tid + j*G1_THREADS;
        if (i < 1152) {
            int row = i >> 3, q = i & 7;
            cpa16(sbB + SWZ((uint32_t)(row*128 + q*16)), w + row*64 + q*8, 16u);
        }
    }
}

__global__ __launch_bounds__(G1_THREADS, 1) void k_gemm1(const float* __restrict__ bg,
                                                         const float* __restrict__ bb,
                                                         const float* __restrict__ bm,
                                                         const float* __restrict__ bv) {
    extern __shared__ char smem[];
    const int tid  = threadIdx.x;
    const int wid  = tid >> 5, lane = tid & 31;
    const int y0   = (blockIdx.x & 63) * 2;
    const int b    = blockIdx.x >> 6;
    const uint32_t sb = smem_u32(smem);

    float* sScale = (float*)(smem + G1_BN);
    float* sMean  = sScale + MIDC;
    float* sBeta  = sMean + MIDC;
    if (tid < MIDC) {
        sScale[tid] = bg[tid] * rsqrtf(bv[tid] + 1e-5f);
        sMean[tid]  = bm[tid];
        sBeta[tid]  = bb[tid];
    }

    const int wm = wid >> 1, wn = wid & 1;
    const int ywarp = wm >> 2;
    const int pxb   = (wm & 3) * 32;

    const int gA = lane >> 3;
    const int arow_off = (lane & 7) + ((gA & 1) << 3);
    const uint32_t acol_g = (uint32_t)((gA >> 1) << 4);
    const uint32_t swzx   = (uint32_t)((lane & 7) << 4);
    const int brow_off = ((gA >> 1) << 3) + (lane & 7);
    const uint32_t bcol_g = (uint32_t)((gA & 1) << 4);
    const int l2 = lane & 15;
    const int b2row_off = 64 + (l2 & 7);
    const uint32_t b2col_g = (uint32_t)((l2 >> 3) << 4);
    const uint32_t swz2   = (uint32_t)((l2 & 7) << 4);

    float acc[2][9][4];
#pragma unroll
    for (int mf = 0; mf < 2; mf++)
#pragma unroll
        for (int nf = 0; nf < 9; nf++)
#pragma unroll
            for (int k = 0; k < 4; k++) acc[mf][nf][k] = 0.f;

    g1_stageA(sb, tid, 0, b, y0);
    g1_stageB(sb + G1_BOFF, tid, 0, 0);
    CPA_COMMIT();

    int s = 0;
    for (int c = 0; c < NCHUNK; c++) {
        if (c > 0) { g1_stageA(sb, tid, c, b, y0); CPA_COMMIT(); }
        for (int t = 0; t < NTAP; t++, s++) {
            if (s + 1 < NTAP*NCHUNK) {
                int t1 = (t + 1 < NTAP) ? t + 1 : 0;
                int c1 = (t + 1 < NTAP) ? c : c + 1;
                g1_stageB(sb + G1_BOFF + (uint32_t)((s + 1) & 1)*G1_BSTG, tid, t1, c1);
                CPA_COMMIT();
                CPA_WAIT1();
            } else {
                CPA_WAIT0();
            }
            __syncthreads();

            const int ky = t / 3, kx = t - ky*3;
            const uint32_t bBase = sb + G1_BOFF + (uint32_t)(s & 1)*G1_BSTG + (uint32_t)(wn*72)*128;
            const int arbase = (ky + ywarp)*132 + pxb + kx;

#pragma unroll
            for (int ks = 0; ks < 4; ks++) {
                uint32_t bh[9][2];
                const uint32_t colB = ((uint32_t)(ks * 32) + bcol_g) ^ swzx;
#pragma unroll
                for (int nf = 0; nf < 8; nf += 2) {
                    uint32_t rb = (uint32_t)(nf * 8 + brow_off) * 128;
                    uint32_t tmp[4];
                    ldsm4(bBase + rb + colB, tmp);
                    bh[nf][0] = tmp[0]; bh[nf][1] = tmp[1];
                    bh[nf+1][0] = tmp[2]; bh[nf+1][1] = tmp[3];
                }
                {
                    const uint32_t colB2 = ((uint32_t)(ks * 32) + b2col_g) ^ swz2;
                    uint32_t rb2 = (uint32_t)b2row_off * 128;
                    ldsm2(bBase + rb2 + colB2, bh[8]);
                }
                const uint32_t colA_base = (uint32_t)(ks * 32) + acol_g;
#pragma unroll
                for (int mf = 0; mf < 2; mf++) {
                    int arow = arbase + mf*16 + arow_off;
                    uint32_t aaddr = sb + (uint32_t)arow*128
                                   + (colA_base ^ (((uint32_t)arow & 7) << 4));
                    uint32_t ah[4];
                    ldsm4(aaddr, ah);
#pragma unroll
                    for (int nf = 0; nf < 9; nf++)
                        mma16816h(acc[mf][nf], ah, bh[nf]);
                }
            }
            __syncthreads();
        }
    }

    // epilogue: BN + GELU -> fp16 NHWC (CPAD2) for gemm2
    const int yout = y0 + ywarp;
#pragma unroll
    for (int mf = 0; mf < 2; mf++)
#pragma unroll
        for (int nf = 0; nf < 9; nf++) {
            int co0 = wn * 72 + nf * 8 + (lane & 3) * 2;
            int x0  = pxb + mf * 16 + (lane >> 2);
#pragma unroll
            for (int hr = 0; hr < 2; hr++) {
                int x = x0 + hr * 8;
                float v0 = acc[mf][nf][hr * 2 + 0];
                float v1 = acc[mf][nf][hr * 2 + 1];
                float g0 = gelu_exact((v0 - sMean[co0]) * sScale[co0] + sBeta[co0]);
                float g1 = gelu_exact((v1 - sMean[co0+1]) * sScale[co0+1] + sBeta[co0+1]);
                __half2 ph; ph.x = __float2half(g0); ph.y = __float2half(g1);
                *(__half2*)&g_midh[((size_t)b*HW + yout*WW + x) * CPAD2 + co0] = ph;
            }
        }
}

// ================= kernel 6: conv2 implicit GEMM pure fp16, 512 threads, M=256 =========
#define G2_ASPL 67584
#define G2_BOFF G2_ASPL
#define G2_BSTG 7168
#define G2_BN   (G2_BOFF + 2*G2_BSTG)   // 81920
#define G2_SMEM (G2_BN + 3*OPC*4 + 64)
#define G2_THREADS 512

__device__ __forceinline__ void g2_stageA(uint32_t sbA, int tid, int c, int b, int y0) {
#pragma unroll
    for (int j = 0; j < 9; j++) {
        int i = tid + j*G2_THREADS;
        if (i < 4224) {
            int row = i >> 3, q = i & 7;
            int yrel = row / 132;
            int pxh  = row - yrel*132;
            int ysrc = y0 - 1 + yrel, xsrc = pxh - 1;
            bool ok = ((unsigned)ysrc < (unsigned)HH) && ((unsigned)xsrc < (unsigned)WW);
            const void* gp = g_midh + ((size_t)((b*HH + (ok?ysrc:0))*WW + (ok?xsrc:0)))*CPAD2 + c*64 + q*8;
            cpa16(sbA + SWZ((uint32_t)(row*128 + q*16)), gp, ok ? 16u : 0u);
        }
    }
}
__device__ __forceinline__ void g2_stageB(uint32_t sbB, int tid, int t, int c) {
    const __half* w = g_w2 + (size_t)(t*3 + c)*OPAD*64;
    if (tid < OPAD*8) {
        int row = tid >> 3, q = tid & 7;
        cpa16(sbB + SWZ((uint32_t)(row*128 + q*16)), w + row*64 + q*8, 16u);
    }
}

__global__ __launch_bounds__(G2_THREADS, 1) void k_gemm2(const float* __restrict__ bg,
                                                         const float* __restrict__ bb,
                                                         const float* __restrict__ bm,
                                                         const float* __restrict__ bv,
                                                         float* __restrict__ dout) {
    extern __shared__ char smem[];
    const int tid  = threadIdx.x;
    const int wid  = tid >> 5, lane = tid & 31;
    const int y0   = (blockIdx.x & 63) * 2;
    const int b    = blockIdx.x >> 6;
    const uint32_t sb = smem_u32(smem);

    float* sScale = (float*)(smem + G2_BN);
    float* sMean  = sScale + OPC;
    float* sBeta  = sMean + OPC;
    if (tid < OPC) {
        sScale[tid] = bg[tid] * rsqrtf(bv[tid] + 1e-5f);
        sMean[tid]  = bm[tid];
        sBeta[tid]  = bb[tid];
    }

    const int ywarp = wid >> 3;          // 0/1
    const int pxb   = (wid & 7) * 16;    // 16 px per warp

    const int gA = lane >> 3;
    const int arow_off = (lane & 7) + ((gA & 1) << 3);
    const uint32_t acol_g = (uint32_t)((gA >> 1) << 4);
    const uint32_t swzx   = (uint32_t)((lane & 7) << 4);
    const int brow_off = ((gA >> 1) << 3) + (lane & 7);
    const uint32_t bcol_g = (uint32_t)((gA & 1) << 4);
    const int l2 = lane & 15;
    const int b2row_off = 48 + (l2 & 7);
    const uint32_t b2col_g = (uint32_t)((l2 >> 3) << 4);
    const uint32_t swz2   = (uint32_t)((l2 & 7) << 4);

    float acc[7][4];
#pragma unroll
    for (int nf = 0; nf < 7; nf++)
#pragma unroll
        for (int k = 0; k < 4; k++) acc[nf][k] = 0.f;

    g2_stageA(sb, tid, 0, b, y0);
    g2_stageB(sb + G2_BOFF, tid, 0, 0);
    CPA_COMMIT();

    int s = 0;
    for (int c = 0; c < 3; c++) {
        if (c > 0) { g2_stageA(sb, tid, c, b, y0); CPA_COMMIT(); }
        for (int t = 0; t < NTAP; t++, s++) {
            if (s + 1 < NTAP*3) {
                int t1 = (t + 1 < NTAP) ? t + 1 : 0;
                int c1 = (t + 1 < NTAP) ? c : c + 1;
                g2_stageB(sb + G2_BOFF + (uint32_t)((s + 1) & 1)*G2_BSTG, tid, t1, c1);
                CPA_COMMIT();
                CPA_WAIT1();
            } else {
                CPA_WAIT0();
            }
            __syncthreads();

            const int ky = t / 3, kx = t - ky*3;
            const uint32_t bBase = sb + G2_BOFF + (uint32_t)(s & 1)*G2_BSTG;
            const int arbase = (ky + ywarp)*132 + pxb + kx;

#pragma unroll
            for (int ks = 0; ks < 4; ks++) {
                uint32_t bh[7][2];
                const uint32_t colB = ((uint32_t)(ks * 32) + bcol_g) ^ swzx;
#pragma unroll
                for (int nf = 0; nf < 6; nf += 2) {
                    uint32_t rb = (uint32_t)(nf * 8 + brow_off) * 128;
                    uint32_t tmp[4];
                    ldsm4(bBase + rb + colB, tmp);
                    bh[nf][0] = tmp[0]; bh[nf][1] = tmp[1];
                    bh[nf+1][0] = tmp[2]; bh[nf+1][1] = tmp[3];
                }
                {
                    const uint32_t colB2 = ((uint32_t)(ks * 32) + b2col_g) ^ swz2;
                    uint32_t rb2 = (uint32_t)b2row_off * 128;
                    ldsm2(bBase + rb2 + colB2, bh[6]);
                }
                const uint32_t colA_base = (uint32_t)(ks * 32) + acol_g;
                {
                    int arow = arbase + arow_off;
                    uint32_t aaddr = sb + (uint32_t)arow*128
                                   + (colA_base ^ (((uint32_t)arow & 7) << 4));
                    uint32_t ah[4];
                    ldsm4(aaddr, ah);
#pragma unroll
                    for (int nf = 0; nf < 7; nf++)
                        mma16816h(acc[nf], ah, bh[nf]);
                }
            }
            __syncthreads();
        }
    }

    const int yout = y0 + ywarp;
#pragma unroll
    for (int nf = 0; nf < 7; nf++) {
        int co0 = nf * 8 + (lane & 3) * 2;
        int x0  = pxb + (lane >> 2);
#pragma unroll
        for (int hr = 0; hr < 2; hr++) {
            int x = x0 + hr * 8;
#pragma unroll
            for (int dc = 0; dc < 2; dc++) {
                int co = co0 + dc;
                if (co < OPC) {
                    float v = acc[nf][hr * 2 + dc];
                    float gel = gelu_exact((v - sMean[co]) * sScale[co] + sBeta[co]);
                    dout[(((size_t)b*OPC + co)*HH + yout)*WW + x] = gel;
                }
            }
        }
    }
}

// ---------------- launch ----------------
extern "C" void kernel_launch(void* const* d_in, const int* in_sizes, int n_in,
                              void* d_out, int out_size) {
    const float* f1    = (const float*)d_in[0];
    const float* f2    = (const float*)d_in[1];
    const float* att_w = (const float*)d_in[2];
    const float* att_b = (const float*)d_in[3];
    const float* c1_w  = (const float*)d_in[4];
    const float* bn1_g = (const float*)d_in[5];
    const float* bn1_b = (const float*)d_in[6];
    const float* bn1_m = (const float*)d_in[7];
    const float* bn1_v = (const float*)d_in[8];
    const float* c2_w  = (const float*)d_in[9];
    const float* bn2_g = (const float*)d_in[10];
    const float* bn2_b = (const float*)d_in[11];
    const float* bn2_m = (const float*)d_in[12];
    const float* bn2_v = (const float*)d_in[13];

    cudaFuncSetAttribute(k_gemm1, cudaFuncAttributeMaxDynamicSharedMemorySize, G1_SMEM);
    cudaFuncSetAttribute(k_gemm2, cudaFuncAttributeMaxDynamicSharedMemorySize, G2_SMEM);

    k_prep<<<PREP_RN_BLKS + PREP_W1_BLKS + PREP_W2_BLKS, 256>>>(f1, c1_w, c2_w);
    k_costvol<<<dim3(WW/64, HH, BB_), 272>>>(f1, f2);
    k_att<<<dim3(WW/32, HH/16, BB_*IP), 256>>>(att_w, att_b);
    k_nhwc<<<dim3(HW/32, (IP+31)/32, BB_), 256>>>();
    k_gemm1<<<BB_*64, G1_THREADS, G1_SMEM>>>(bn1_g, bn1_b, bn1_m, bn1_v);
    k_gemm2<<<BB_*64, G2_THREADS, G2_SMEM>>>(bn2_g, bn2_b, bn2_m, bn2_v, (float*)d_out);
}